// round 16
// baseline (speedup 1.0000x reference)
#include <cuda_runtime.h>
#include <cuda_fp16.h>

#define NN  100000
#define EE  3200000
#define GMAX 128

// ---------------- scratch (no allocations allowed) ----------------
// d_h : (x@W1)*dinv[node]  (fp16, pre-scaled at creation)
// d_h2: (relu(h1)@W2 + rc)*dinv[node]  (fp16, pre-scaled at creation)
__device__ __align__(16) __half d_h [NN * 64];
__device__ __align__(16) __half d_h2[NN * 64];
__device__ float d_dinv[NN];
__device__ int   d_ideg [NN];
__device__ int   d_start[NN];
__device__ int   d_cur  [NN];
__device__ __align__(16) int d_esrc [EE];
__device__ int   d_bsum [256];
__device__ int   d_root [GMAX];
__device__ __align__(16) float d_rc    [GMAX * 64];
__device__ __align__(16) float d_rooth1[GMAX * 64];
__device__ __align__(16) float d_sums  [GMAX * 64];
__device__ int   d_cnt [GMAX];

// half helpers ---------------------------------------------------------
__device__ __forceinline__ void store_h4(__half* base, float4 v) {
    union { __half2 h2[2]; uint2 u; } pk;
    pk.h2[0] = __floats2half2_rn(v.x, v.y);
    pk.h2[1] = __floats2half2_rn(v.z, v.w);
    *reinterpret_cast<uint2*>(base) = pk.u;
}
__device__ __forceinline__ float4 load_h4(const __half* base) {
    uint2 raw = __ldg(reinterpret_cast<const uint2*>(base));
    __half2 a = *reinterpret_cast<__half2*>(&raw.x);
    __half2 b = *reinterpret_cast<__half2*>(&raw.y);
    float2 f0 = __half22float2(a), f1 = __half22float2(b);
    return make_float4(f0.x, f0.y, f1.x, f1.y);
}
__device__ __forceinline__ void acc4(float4& a, float4 v) {
    a.x += v.x; a.y += v.y; a.z += v.z; a.w += v.w;
}

// 16 lanes/node edge gather. Index stream vectorized: 2x LDG.128 per
// 8-edge batch (was 8x LDG.32) -> ~24% fewer L1tex wavefronts. CSR
// offsets are arbitrary, so peel to int4 alignment first.
__device__ __forceinline__ float4 edge_gather(const __half* __restrict__ rows,
                                              int s0, int deg, int q) {
    float4 a0 = make_float4(0.f, 0.f, 0.f, 0.f);
    float4 a1 = make_float4(0.f, 0.f, 0.f, 0.f);
    const int* ep = d_esrc + s0;
    int qo = q << 2;
    int e = 0;
    int head = (4 - (s0 & 3)) & 3;
    if (head > deg) head = deg;
    for (; e < head; e++) {
        int s = __ldg(ep + e);
        acc4(a0, load_h4(rows + (size_t)s * 64 + qo));
    }
    for (; e + 8 <= deg; e += 8) {
        int4 ia = __ldg(reinterpret_cast<const int4*>(ep + e));
        int4 ib = __ldg(reinterpret_cast<const int4*>(ep + e + 4));
        float4 v0 = load_h4(rows + (size_t)ia.x * 64 + qo);
        float4 v1 = load_h4(rows + (size_t)ia.y * 64 + qo);
        float4 v2 = load_h4(rows + (size_t)ia.z * 64 + qo);
        float4 v3 = load_h4(rows + (size_t)ia.w * 64 + qo);
        float4 v4 = load_h4(rows + (size_t)ib.x * 64 + qo);
        float4 v5 = load_h4(rows + (size_t)ib.y * 64 + qo);
        float4 v6 = load_h4(rows + (size_t)ib.z * 64 + qo);
        float4 v7 = load_h4(rows + (size_t)ib.w * 64 + qo);
        acc4(a0, v0); acc4(a1, v1); acc4(a0, v2); acc4(a1, v3);
        acc4(a0, v4); acc4(a1, v5); acc4(a0, v6); acc4(a1, v7);
    }
    for (; e < deg; e++) {
        int s = __ldg(ep + e);
        acc4(a0, load_h4(rows + (size_t)s * 64 + qo));
    }
    a0.x += a1.x; a0.y += a1.y; a0.z += a1.z; a0.w += a1.w;
    return a0;
}

// ---------------- setup ----------------

__global__ void k_init(int n, int g) {
    int i = blockIdx.x * blockDim.x + threadIdx.x;
    if (i < n) d_ideg[i] = 0;
    if (i < g * 64) d_sums[i] = 0.0f;
    if (i < g) { d_cnt[i] = 0; d_root[i] = n - 1; }
}

// fused: hist | root scan
__global__ void k_work1(const int* __restrict__ dst, const int* __restrict__ batch,
                        int e, int n, int nbE) {
    int role_b = blockIdx.x;
    if (role_b < nbE) {
        int i = role_b * 256 + threadIdx.x;
        if (i < e) atomicAdd(&d_ideg[dst[i]], 1);
        return;
    }
    role_b -= nbE;
    int i = role_b * 256 + threadIdx.x;
    if (i < n) {
        int g = batch[i];
        atomicMin(&d_root[g], i);
        atomicAdd(&d_cnt[g], 1);
    }
}

// block scan: 1024 elems / block
__global__ void k_scan1(int n) {
    __shared__ int sm[256];
    int t = threadIdx.x, b = blockIdx.x;
    int base = b * 1024 + t * 4;
    int v[4]; int s = 0;
#pragma unroll
    for (int u = 0; u < 4; u++) {
        int i = base + u;
        v[u] = (i < n) ? d_ideg[i] : 0;
        s += v[u];
    }
    sm[t] = s; __syncthreads();
#pragma unroll
    for (int off = 1; off < 256; off <<= 1) {
        int x = (t >= off) ? sm[t - off] : 0;
        __syncthreads();
        sm[t] += x;
        __syncthreads();
    }
    int excl = sm[t] - s;
#pragma unroll
    for (int u = 0; u < 4; u++) {
        int i = base + u;
        if (i < n) d_start[i] = excl;
        excl += v[u];
    }
    if (t == 255) d_bsum[b] = sm[255];
}

// fused scan2+scan3
__global__ void k_scan23(int n, int nb) {
    __shared__ int sm[128];
    __shared__ int boff;
    int t = threadIdx.x, b = blockIdx.x;
    if (t < 128) sm[t] = (t < nb) ? d_bsum[t] : 0;
    __syncthreads();
#pragma unroll
    for (int off = 1; off < 128; off <<= 1) {
        int x = (t < 128 && t >= off) ? sm[t - off] : 0;
        __syncthreads();
        if (t < 128) sm[t] += x;
        __syncthreads();
    }
    if (t == 0) boff = (b == 0) ? 0 : sm[b - 1];
    __syncthreads();
    int base = b * 1024 + t * 4;
#pragma unroll
    for (int u = 0; u < 4; u++) {
        int i = base + u;
        if (i < n) {
            int st = d_start[i] + boff;
            d_start[i] = st;
            d_cur[i] = st;
            d_dinv[i] = rsqrtf((float)d_ideg[i] + 1.0f);
        }
    }
}

// fused: place | gemm1 (h = (x@W1)*dinv, fp16 out) | rc
__global__ void k_work2(const int* __restrict__ src, const int* __restrict__ dst,
                        const float* __restrict__ x, const float* __restrict__ W1,
                        const float* __restrict__ W2,
                        int e, int n, int g, int nbE, int nbG) {
    int role_b = blockIdx.x;
    if (role_b < nbE) {
        int i = role_b * 256 + threadIdx.x;
        if (i < e) {
            int d = dst[i];
            int pos = atomicAdd(&d_cur[d], 1);
            d_esrc[pos] = src[i];
        }
        return;
    }
    role_b -= nbE;
    if (role_b < nbG) {
        int node = (role_b * 256 + threadIdx.x) >> 4;
        int q  = threadIdx.x & 15;
        int nl = threadIdx.x >> 4;
        __shared__ float4 xs[16][32];
        bool valid = node < n;
        int nd = valid ? node : (n - 1);
        const float4* xr = reinterpret_cast<const float4*>(x + (size_t)nd * 128);
        xs[nl][q]      = xr[q];
        xs[nl][16 + q] = xr[16 + q];
        __syncwarp();
        const float4* W = reinterpret_cast<const float4*>(W1);
        float4 acc = make_float4(0.f, 0.f, 0.f, 0.f);
#pragma unroll 8
        for (int k4 = 0; k4 < 32; k4++) {
            float4 xv = xs[nl][k4];
            float4 w0 = __ldg(&W[(k4 * 4 + 0) * 16 + q]);
            float4 w1 = __ldg(&W[(k4 * 4 + 1) * 16 + q]);
            float4 w2 = __ldg(&W[(k4 * 4 + 2) * 16 + q]);
            float4 w3 = __ldg(&W[(k4 * 4 + 3) * 16 + q]);
            acc.x = fmaf(xv.x, w0.x, acc.x); acc.y = fmaf(xv.x, w0.y, acc.y);
            acc.z = fmaf(xv.x, w0.z, acc.z); acc.w = fmaf(xv.x, w0.w, acc.w);
            acc.x = fmaf(xv.y, w1.x, acc.x); acc.y = fmaf(xv.y, w1.y, acc.y);
            acc.z = fmaf(xv.y, w1.z, acc.z); acc.w = fmaf(xv.y, w1.w, acc.w);
            acc.x = fmaf(xv.z, w2.x, acc.x); acc.y = fmaf(xv.z, w2.y, acc.y);
            acc.z = fmaf(xv.z, w2.z, acc.z); acc.w = fmaf(xv.z, w2.w, acc.w);
            acc.x = fmaf(xv.w, w3.x, acc.x); acc.y = fmaf(xv.w, w3.y, acc.y);
            acc.z = fmaf(xv.w, w3.z, acc.z); acc.w = fmaf(xv.w, w3.w, acc.w);
        }
        if (valid) {
            float di = d_dinv[node];
            acc.x *= di; acc.y *= di; acc.z *= di; acc.w *= di;
            store_h4(d_h + (size_t)node * 64 + (q << 2), acc);
        }
        return;
    }
    role_b -= nbG;
    int gi = role_b * 4 + (threadIdx.x >> 6);
    int j  = threadIdx.x & 63;
    __shared__ float xs2[4][128];
    if (gi >= g) return;
    int grp = threadIdx.x >> 6;
    int r = d_root[gi];
    xs2[grp][j]      = fmaxf(x[(size_t)r * 128 + j], 0.0f);
    xs2[grp][64 + j] = fmaxf(x[(size_t)r * 128 + 64 + j], 0.0f);
    __syncthreads();
    float acc = 0.0f;
#pragma unroll 8
    for (int k = 0; k < 128; k++)
        acc = fmaf(xs2[grp][k], __ldg(&W2[(64 + k) * 64 + j]), acc);
    d_rc[gi * 64 + j] = acc;
}

// ---------------- fused gather1 + gemm2 (16 lanes/node) ----------------
__global__ void k_gather1(const float* __restrict__ b1, const int* __restrict__ batch,
                          const float* __restrict__ W2, int n) {
    int node = (blockIdx.x * 256 + threadIdx.x) >> 4;
    int q  = threadIdx.x & 15;
    int nl = threadIdx.x >> 4;
    __shared__ float4 zs[16][16];
    bool valid = node < n;
    int nd = valid ? node : (n - 1);
    float di = d_dinv[nd];
    int s0 = d_start[nd];
    int deg = valid ? d_ideg[nd] : 0;

    float4 acc = edge_gather(d_h, s0, deg, q);

    float4 hv = load_h4(d_h + (size_t)nd * 64 + (q << 2));
    float4 bb = *reinterpret_cast<const float4*>(b1 + (q << 2));
    float4 r;
    r.x = fmaf(acc.x + hv.x, di, bb.x);
    r.y = fmaf(acc.y + hv.y, di, bb.y);
    r.z = fmaf(acc.z + hv.z, di, bb.z);
    r.w = fmaf(acc.w + hv.w, di, bb.w);

    int g = batch[nd];
    if (valid && d_root[g] == node)
        *reinterpret_cast<float4*>(d_rooth1 + g * 64 + (q << 2)) = r;

    float4 z;
    z.x = fmaxf(r.x, 0.f); z.y = fmaxf(r.y, 0.f);
    z.z = fmaxf(r.z, 0.f); z.w = fmaxf(r.w, 0.f);
    zs[nl][q] = z;
    __syncwarp();

    const float4* W = reinterpret_cast<const float4*>(W2);
    float4 a2 = *reinterpret_cast<const float4*>(d_rc + g * 64 + (q << 2));
#pragma unroll 4
    for (int k4 = 0; k4 < 16; k4++) {
        float4 zv = zs[nl][k4];
        float4 w0 = __ldg(&W[(k4 * 4 + 0) * 16 + q]);
        float4 w1 = __ldg(&W[(k4 * 4 + 1) * 16 + q]);
        float4 w2 = __ldg(&W[(k4 * 4 + 2) * 16 + q]);
        float4 w3 = __ldg(&W[(k4 * 4 + 3) * 16 + q]);
        a2.x = fmaf(zv.x, w0.x, a2.x); a2.y = fmaf(zv.x, w0.y, a2.y);
        a2.z = fmaf(zv.x, w0.z, a2.z); a2.w = fmaf(zv.x, w0.w, a2.w);
        a2.x = fmaf(zv.y, w1.x, a2.x); a2.y = fmaf(zv.y, w1.y, a2.y);
        a2.z = fmaf(zv.y, w1.z, a2.z); a2.w = fmaf(zv.y, w1.w, a2.w);
        a2.x = fmaf(zv.z, w2.x, a2.x); a2.y = fmaf(zv.z, w2.y, a2.y);
        a2.z = fmaf(zv.z, w2.z, a2.z); a2.w = fmaf(zv.z, w2.w, a2.w);
        a2.x = fmaf(zv.w, w3.x, a2.x); a2.y = fmaf(zv.w, w3.y, a2.y);
        a2.z = fmaf(zv.w, w3.z, a2.z); a2.w = fmaf(zv.w, w3.w, a2.w);
    }
    if (valid) {
        a2.x *= di; a2.y *= di; a2.z *= di; a2.w *= di;  // pre-scale for gather2
        store_h4(d_h2 + (size_t)node * 64 + (q << 2), a2);
    }
}

// v = relu((gathered + h2_s[nd]) * dinv + b2); block-reduce into sums
__global__ void k_gather2(const float* __restrict__ b2, const int* __restrict__ batch, int n) {
    int node = (blockIdx.x * 256 + threadIdx.x) >> 4;
    int q = threadIdx.x & 15;
    bool valid = node < n;
    int nd = valid ? node : (n - 1);
    float di = d_dinv[nd];
    int s0 = d_start[nd];
    int deg = valid ? d_ideg[nd] : 0;

    float4 acc = edge_gather(d_h2, s0, deg, q);

    int g = batch[nd];
    float4 v = make_float4(0.f, 0.f, 0.f, 0.f);
    if (valid) {
        float4 hv = load_h4(d_h2 + (size_t)nd * 64 + (q << 2));
        float4 bb = *reinterpret_cast<const float4*>(b2 + (q << 2));
        v.x = fmaxf(fmaf(acc.x + hv.x, di, bb.x), 0.f);
        v.y = fmaxf(fmaf(acc.y + hv.y, di, bb.y), 0.f);
        v.z = fmaxf(fmaf(acc.z + hv.z, di, bb.z), 0.f);
        v.w = fmaxf(fmaf(acc.w + hv.w, di, bb.w), 0.f);
    }
    __shared__ float4 sv[256];
    __shared__ int sg[16];
    int grp = threadIdx.x >> 4;
    if (q == 0) sg[grp] = g;
    sv[threadIdx.x] = v;
    __syncthreads();
    int uni = __syncthreads_and(g == sg[0]);
    if (uni) {
#pragma unroll
        for (int st = 8; st >= 1; st >>= 1) {
            if (grp < st) {
                float4 o = sv[threadIdx.x + (st << 4)];
                sv[threadIdx.x].x += o.x; sv[threadIdx.x].y += o.y;
                sv[threadIdx.x].z += o.z; sv[threadIdx.x].w += o.w;
            }
            __syncthreads();
        }
        if (grp == 0) {
            float4 r = sv[q];
            float* p = d_sums + sg[0] * 64 + (q << 2);
            asm volatile("red.global.add.v4.f32 [%0], {%1,%2,%3,%4};"
                         :: "l"(p), "f"(r.x), "f"(r.y), "f"(r.z), "f"(r.w) : "memory");
        }
    } else {
        float* p = d_sums + g * 64 + (q << 2);
        asm volatile("red.global.add.v4.f32 [%0], {%1,%2,%3,%4};"
                     :: "l"(p), "f"(v.x), "f"(v.y), "f"(v.z), "f"(v.w) : "memory");
    }
}

__global__ void k_out(float* __restrict__ out) {
    int g = blockIdx.x;
    int j = threadIdx.x;
    float c = (float)d_cnt[g];
    float val;
    if (j < 64) val = d_sums[g * 64 + j] / fmaxf(c, 1.0f);
    else        val = (c > 0.0f) ? d_rooth1[g * 64 + (j - 64)] : 0.0f;
    out[g * 128 + j] = val;
}

// ---------------- launcher (single stream, no allocations) ----------------
extern "C" void kernel_launch(void* const* d_in, const int* in_sizes, int n_in,
                              void* d_out, int out_size) {
    const float* x     = (const float*)d_in[0];
    const int*   ei    = (const int*)d_in[1];    // int32 (JAX x64 disabled)
    const int*   batch = (const int*)d_in[2];
    const float* W1    = (const float*)d_in[3];
    const float* b1    = (const float*)d_in[4];
    const float* W2    = (const float*)d_in[5];
    const float* b2    = (const float*)d_in[6];
    float*       out   = (float*)d_out;

    int n = in_sizes[0] / 128;   // 100000
    int e = in_sizes[1] / 2;     // 3200000
    int g = out_size / 128;      // 128

    const int* src = ei;
    const int* dst = ei + e;

    int nb_n    = (n + 255) / 256;
    int nb_e    = (e + 255) / 256;
    int nb_scan = (n + 1023) / 1024;
    int nb_g16  = (n * 16 + 255) / 256;
    int nb_rc   = (g + 3) / 4;

    k_init    <<<nb_n, 256>>>(n, g);
    k_work1   <<<nb_e + nb_n, 256>>>(dst, batch, e, n, nb_e);
    k_scan1   <<<nb_scan, 256>>>(n);
    k_scan23  <<<nb_scan, 256>>>(n, nb_scan);
    k_work2   <<<nb_e + nb_g16 + nb_rc, 256>>>(src, dst, x, W1, W2, e, n, g, nb_e, nb_g16);
    k_gather1 <<<nb_g16, 256>>>(b1, batch, W2, n);
    k_gather2 <<<nb_g16, 256>>>(b2, batch, n);
    k_out     <<<g, 128>>>(out);
}

// round 17
// speedup vs baseline: 1.2282x; 1.2282x over previous
#include <cuda_runtime.h>
#include <cuda_fp16.h>

#define NN  100000
#define EE  3200000
#define GMAX 128

// ---------------- scratch (no allocations allowed) ----------------
// d_h : (x@W1)*dinv[node]  (fp16, pre-scaled at creation)
// d_h2: (relu(h1)@W2 + rc)*dinv[node]  (fp16, pre-scaled at creation)
__device__ __align__(16) __half d_h [NN * 64];
__device__ __align__(16) __half d_h2[NN * 64];
__device__ float d_dinv[NN];
__device__ int   d_ideg [NN];
__device__ int   d_start[NN];
__device__ int   d_cur  [NN];
__device__ int   d_esrc [EE];
__device__ int   d_bsum [256];
__device__ int   d_root [GMAX];
// fp16 packed weights: one uint4 per (k-pair, lane) = 2 rows x 4 cols
// index: ((k>>1)*16 + (c>>2))*8 + (k&1)*4 + (c&3)
__device__ __align__(16) __half d_W1h[128 * 64];
__device__ __align__(16) __half d_W2h[64 * 64];
__device__ __align__(16) float d_rc    [GMAX * 64];
__device__ __align__(16) float d_rooth1[GMAX * 64];
__device__ __align__(16) float d_sums  [GMAX * 64];
__device__ int   d_cnt [GMAX];

// half helpers ---------------------------------------------------------
__device__ __forceinline__ void store_h4(__half* base, float4 v) {
    union { __half2 h2[2]; uint2 u; } pk;
    pk.h2[0] = __floats2half2_rn(v.x, v.y);
    pk.h2[1] = __floats2half2_rn(v.z, v.w);
    *reinterpret_cast<uint2*>(base) = pk.u;
}
__device__ __forceinline__ float4 load_h4(const __half* base) {
    uint2 raw = __ldg(reinterpret_cast<const uint2*>(base));
    __half2 a = *reinterpret_cast<__half2*>(&raw.x);
    __half2 b = *reinterpret_cast<__half2*>(&raw.y);
    float2 f0 = __half22float2(a), f1 = __half22float2(b);
    return make_float4(f0.x, f0.y, f1.x, f1.y);
}
__device__ __forceinline__ void acc4(float4& a, float4 v) {
    a.x += v.x; a.y += v.y; a.z += v.z; a.w += v.w;
}

// fp16-weight FMA step: one uint4 = 2 k-rows x 4 cols for this lane.
__device__ __forceinline__ void wfma2(float4& acc, uint4 raw, float x0, float x1) {
    float2 a = __half22float2(*reinterpret_cast<__half2*>(&raw.x));
    float2 b = __half22float2(*reinterpret_cast<__half2*>(&raw.y));
    float2 c = __half22float2(*reinterpret_cast<__half2*>(&raw.z));
    float2 d = __half22float2(*reinterpret_cast<__half2*>(&raw.w));
    acc.x = fmaf(x0, a.x, acc.x); acc.y = fmaf(x0, a.y, acc.y);
    acc.z = fmaf(x0, b.x, acc.z); acc.w = fmaf(x0, b.y, acc.w);
    acc.x = fmaf(x1, c.x, acc.x); acc.y = fmaf(x1, c.y, acc.y);
    acc.z = fmaf(x1, d.x, acc.z); acc.w = fmaf(x1, d.y, acc.w);
}

// 16 lanes/node edge gather (the proven 346us config): 8 independent idx
// loads then 8 independent row loads; two accumulators.
__device__ __forceinline__ float4 edge_gather(const __half* __restrict__ rows,
                                              int s0, int deg, int q) {
    float4 a0 = make_float4(0.f, 0.f, 0.f, 0.f);
    float4 a1 = make_float4(0.f, 0.f, 0.f, 0.f);
    const int* ep = d_esrc + s0;
    int qo = q << 2;
    int e = 0;
    for (; e + 8 <= deg; e += 8) {
        int i0 = __ldg(ep + e + 0);
        int i1 = __ldg(ep + e + 1);
        int i2 = __ldg(ep + e + 2);
        int i3 = __ldg(ep + e + 3);
        int i4 = __ldg(ep + e + 4);
        int i5 = __ldg(ep + e + 5);
        int i6 = __ldg(ep + e + 6);
        int i7 = __ldg(ep + e + 7);
        float4 v0 = load_h4(rows + (size_t)i0 * 64 + qo);
        float4 v1 = load_h4(rows + (size_t)i1 * 64 + qo);
        float4 v2 = load_h4(rows + (size_t)i2 * 64 + qo);
        float4 v3 = load_h4(rows + (size_t)i3 * 64 + qo);
        float4 v4 = load_h4(rows + (size_t)i4 * 64 + qo);
        float4 v5 = load_h4(rows + (size_t)i5 * 64 + qo);
        float4 v6 = load_h4(rows + (size_t)i6 * 64 + qo);
        float4 v7 = load_h4(rows + (size_t)i7 * 64 + qo);
        acc4(a0, v0); acc4(a1, v1); acc4(a0, v2); acc4(a1, v3);
        acc4(a0, v4); acc4(a1, v5); acc4(a0, v6); acc4(a1, v7);
    }
    for (; e < deg; e++) {
        int s = __ldg(ep + e);
        acc4(a0, load_h4(rows + (size_t)s * 64 + qo));
    }
    a0.x += a1.x; a0.y += a1.y; a0.z += a1.z; a0.w += a1.w;
    return a0;
}

// ---------------- setup ----------------

// init + pack fp16 weights (deterministic every call)
__global__ void k_init(const float* __restrict__ W1, const float* __restrict__ W2,
                       int n, int g) {
    int i = blockIdx.x * blockDim.x + threadIdx.x;
    if (i < n) d_ideg[i] = 0;
    if (i < g * 64) d_sums[i] = 0.0f;
    if (i < g) { d_cnt[i] = 0; d_root[i] = n - 1; }
    if (i < 128 * 64) {
        int k = i >> 6, c = i & 63;
        d_W1h[(((k >> 1) * 16 + (c >> 2)) << 3) + ((k & 1) << 2) + (c & 3)] =
            __float2half(W1[i]);
        if (i < 64 * 64)
            d_W2h[(((k >> 1) * 16 + (c >> 2)) << 3) + ((k & 1) << 2) + (c & 3)] =
                __float2half(W2[i]);
    }
}

// fused: hist | root scan
__global__ void k_work1(const int* __restrict__ dst, const int* __restrict__ batch,
                        int e, int n, int nbE) {
    int role_b = blockIdx.x;
    if (role_b < nbE) {
        int i = role_b * 256 + threadIdx.x;
        if (i < e) atomicAdd(&d_ideg[dst[i]], 1);
        return;
    }
    role_b -= nbE;
    int i = role_b * 256 + threadIdx.x;
    if (i < n) {
        int g = batch[i];
        atomicMin(&d_root[g], i);
        atomicAdd(&d_cnt[g], 1);
    }
}

// block scan: 1024 elems / block
__global__ void k_scan1(int n) {
    __shared__ int sm[256];
    int t = threadIdx.x, b = blockIdx.x;
    int base = b * 1024 + t * 4;
    int v[4]; int s = 0;
#pragma unroll
    for (int u = 0; u < 4; u++) {
        int i = base + u;
        v[u] = (i < n) ? d_ideg[i] : 0;
        s += v[u];
    }
    sm[t] = s; __syncthreads();
#pragma unroll
    for (int off = 1; off < 256; off <<= 1) {
        int x = (t >= off) ? sm[t - off] : 0;
        __syncthreads();
        sm[t] += x;
        __syncthreads();
    }
    int excl = sm[t] - s;
#pragma unroll
    for (int u = 0; u < 4; u++) {
        int i = base + u;
        if (i < n) d_start[i] = excl;
        excl += v[u];
    }
    if (t == 255) d_bsum[b] = sm[255];
}

// fused scan2+scan3
__global__ void k_scan23(int n, int nb) {
    __shared__ int sm[128];
    __shared__ int boff;
    int t = threadIdx.x, b = blockIdx.x;
    if (t < 128) sm[t] = (t < nb) ? d_bsum[t] : 0;
    __syncthreads();
#pragma unroll
    for (int off = 1; off < 128; off <<= 1) {
        int x = (t < 128 && t >= off) ? sm[t - off] : 0;
        __syncthreads();
        if (t < 128) sm[t] += x;
        __syncthreads();
    }
    if (t == 0) boff = (b == 0) ? 0 : sm[b - 1];
    __syncthreads();
    int base = b * 1024 + t * 4;
#pragma unroll
    for (int u = 0; u < 4; u++) {
        int i = base + u;
        if (i < n) {
            int st = d_start[i] + boff;
            d_start[i] = st;
            d_cur[i] = st;
            d_dinv[i] = rsqrtf((float)d_ideg[i] + 1.0f);
        }
    }
}

// fused: place | gemm1 (h = (x@W1h)*dinv, fp16 weights+out) | rc
__global__ void k_work2(const int* __restrict__ src, const int* __restrict__ dst,
                        const float* __restrict__ x, const float* __restrict__ W2,
                        int e, int n, int g, int nbE, int nbG) {
    int role_b = blockIdx.x;
    if (role_b < nbE) {
        int i = role_b * 256 + threadIdx.x;
        if (i < e) {
            int d = dst[i];
            int pos = atomicAdd(&d_cur[d], 1);
            d_esrc[pos] = src[i];
        }
        return;
    }
    role_b -= nbE;
    if (role_b < nbG) {
        int node = (role_b * 256 + threadIdx.x) >> 4;
        int q  = threadIdx.x & 15;
        int nl = threadIdx.x >> 4;
        __shared__ float4 xs[16][32];
        bool valid = node < n;
        int nd = valid ? node : (n - 1);
        const float4* xr = reinterpret_cast<const float4*>(x + (size_t)nd * 128);
        xs[nl][q]      = xr[q];
        xs[nl][16 + q] = xr[16 + q];
        __syncwarp();
        const uint4* Wp = reinterpret_cast<const uint4*>(d_W1h);
        const float* xf = reinterpret_cast<const float*>(xs[nl]);
        float4 acc = make_float4(0.f, 0.f, 0.f, 0.f);
#pragma unroll 8
        for (int k2 = 0; k2 < 64; k2++) {
            uint4 raw = __ldg(&Wp[k2 * 16 + q]);
            wfma2(acc, raw, xf[2 * k2], xf[2 * k2 + 1]);
        }
        if (valid) {
            float di = d_dinv[node];
            acc.x *= di; acc.y *= di; acc.z *= di; acc.w *= di;
            store_h4(d_h + (size_t)node * 64 + (q << 2), acc);
        }
        return;
    }
    role_b -= nbG;
    int gi = role_b * 4 + (threadIdx.x >> 6);
    int j  = threadIdx.x & 63;
    __shared__ float xs2[4][128];
    if (gi >= g) return;
    int grp = threadIdx.x >> 6;
    int r = d_root[gi];
    xs2[grp][j]      = fmaxf(x[(size_t)r * 128 + j], 0.0f);
    xs2[grp][64 + j] = fmaxf(x[(size_t)r * 128 + 64 + j], 0.0f);
    __syncthreads();
    float acc = 0.0f;
#pragma unroll 8
    for (int k = 0; k < 128; k++)
        acc = fmaf(xs2[grp][k], __ldg(&W2[(64 + k) * 64 + j]), acc);
    d_rc[gi * 64 + j] = acc;
}

// ---------------- fused gather1 + gemm2 (16 lanes/node, fp16 W2) --------
__global__ void k_gather1(const float* __restrict__ b1, const int* __restrict__ batch,
                          int n) {
    int node = (blockIdx.x * 256 + threadIdx.x) >> 4;
    int q  = threadIdx.x & 15;
    int nl = threadIdx.x >> 4;
    __shared__ float4 zs[16][16];
    bool valid = node < n;
    int nd = valid ? node : (n - 1);
    float di = d_dinv[nd];
    int s0 = d_start[nd];
    int deg = valid ? d_ideg[nd] : 0;

    float4 acc = edge_gather(d_h, s0, deg, q);

    float4 hv = load_h4(d_h + (size_t)nd * 64 + (q << 2));
    float4 bb = *reinterpret_cast<const float4*>(b1 + (q << 2));
    float4 r;
    r.x = fmaf(acc.x + hv.x, di, bb.x);
    r.y = fmaf(acc.y + hv.y, di, bb.y);
    r.z = fmaf(acc.z + hv.z, di, bb.z);
    r.w = fmaf(acc.w + hv.w, di, bb.w);

    int g = batch[nd];
    if (valid && d_root[g] == node)
        *reinterpret_cast<float4*>(d_rooth1 + g * 64 + (q << 2)) = r;

    float4 z;
    z.x = fmaxf(r.x, 0.f); z.y = fmaxf(r.y, 0.f);
    z.z = fmaxf(r.z, 0.f); z.w = fmaxf(r.w, 0.f);
    zs[nl][q] = z;
    __syncwarp();

    const uint4* Wp = reinterpret_cast<const uint4*>(d_W2h);
    float4 a2 = *reinterpret_cast<const float4*>(d_rc + g * 64 + (q << 2));
    const float* zf = reinterpret_cast<const float*>(zs[nl]);
#pragma unroll 8
    for (int k2 = 0; k2 < 32; k2++) {
        uint4 raw = __ldg(&Wp[k2 * 16 + q]);
        wfma2(a2, raw, zf[2 * k2], zf[2 * k2 + 1]);
    }
    if (valid) {
        a2.x *= di; a2.y *= di; a2.z *= di; a2.w *= di;  // pre-scale for gather2
        store_h4(d_h2 + (size_t)node * 64 + (q << 2), a2);
    }
}

// v = relu((gathered + h2_s[nd]) * dinv + b2); block-reduce into sums
__global__ void k_gather2(const float* __restrict__ b2, const int* __restrict__ batch, int n) {
    int node = (blockIdx.x * 256 + threadIdx.x) >> 4;
    int q = threadIdx.x & 15;
    bool valid = node < n;
    int nd = valid ? node : (n - 1);
    float di = d_dinv[nd];
    int s0 = d_start[nd];
    int deg = valid ? d_ideg[nd] : 0;

    float4 acc = edge_gather(d_h2, s0, deg, q);

    int g = batch[nd];
    float4 v = make_float4(0.f, 0.f, 0.f, 0.f);
    if (valid) {
        float4 hv = load_h4(d_h2 + (size_t)nd * 64 + (q << 2));
        float4 bb = *reinterpret_cast<const float4*>(b2 + (q << 2));
        v.x = fmaxf(fmaf(acc.x + hv.x, di, bb.x), 0.f);
        v.y = fmaxf(fmaf(acc.y + hv.y, di, bb.y), 0.f);
        v.z = fmaxf(fmaf(acc.z + hv.z, di, bb.z), 0.f);
        v.w = fmaxf(fmaf(acc.w + hv.w, di, bb.w), 0.f);
    }
    __shared__ float4 sv[256];
    __shared__ int sg[16];
    int grp = threadIdx.x >> 4;
    if (q == 0) sg[grp] = g;
    sv[threadIdx.x] = v;
    __syncthreads();
    int uni = __syncthreads_and(g == sg[0]);
    if (uni) {
#pragma unroll
        for (int st = 8; st >= 1; st >>= 1) {
            if (grp < st) {
                float4 o = sv[threadIdx.x + (st << 4)];
                sv[threadIdx.x].x += o.x; sv[threadIdx.x].y += o.y;
                sv[threadIdx.x].z += o.z; sv[threadIdx.x].w += o.w;
            }
            __syncthreads();
        }
        if (grp == 0) {
            float4 r = sv[q];
            float* p = d_sums + sg[0] * 64 + (q << 2);
            asm volatile("red.global.add.v4.f32 [%0], {%1,%2,%3,%4};"
                         :: "l"(p), "f"(r.x), "f"(r.y), "f"(r.z), "f"(r.w) : "memory");
        }
    } else {
        float* p = d_sums + g * 64 + (q << 2);
        asm volatile("red.global.add.v4.f32 [%0], {%1,%2,%3,%4};"
                     :: "l"(p), "f"(v.x), "f"(v.y), "f"(v.z), "f"(v.w) : "memory");
    }
}

__global__ void k_out(float* __restrict__ out) {
    int g = blockIdx.x;
    int j = threadIdx.x;
    float c = (float)d_cnt[g];
    float val;
    if (j < 64) val = d_sums[g * 64 + j] / fmaxf(c, 1.0f);
    else        val = (c > 0.0f) ? d_rooth1[g * 64 + (j - 64)] : 0.0f;
    out[g * 128 + j] = val;
}

// ---------------- launcher (single stream, no allocations) ----------------
extern "C" void kernel_launch(void* const* d_in, const int* in_sizes, int n_in,
                              void* d_out, int out_size) {
    const float* x     = (const float*)d_in[0];
    const int*   ei    = (const int*)d_in[1];    // int32 (JAX x64 disabled)
    const int*   batch = (const int*)d_in[2];
    const float* W1    = (const float*)d_in[3];
    const float* b1    = (const float*)d_in[4];
    const float* W2    = (const float*)d_in[5];
    const float* b2    = (const float*)d_in[6];
    float*       out   = (float*)d_out;

    int n = in_sizes[0] / 128;   // 100000
    int e = in_sizes[1] / 2;     // 3200000
    int g = out_size / 128;      // 128

    const int* src = ei;
    const int* dst = ei + e;

    int nb_n    = (n + 255) / 256;
    int nb_e    = (e + 255) / 256;
    int nb_scan = (n + 1023) / 1024;
    int nb_g16  = (n * 16 + 255) / 256;
    int nb_rc   = (g + 3) / 4;

    k_init    <<<nb_n, 256>>>(W1, W2, n, g);
    k_work1   <<<nb_e + nb_n, 256>>>(dst, batch, e, n, nb_e);
    k_scan1   <<<nb_scan, 256>>>(n);
    k_scan23  <<<nb_scan, 256>>>(n, nb_scan);
    k_work2   <<<nb_e + nb_g16 + nb_rc, 256>>>(src, dst, x, W2, e, n, g, nb_e, nb_g16);
    k_gather1 <<<nb_g16, 256>>>(b1, batch, n);
    k_gather2 <<<nb_g16, 256>>>(b2, batch, n);
    k_out     <<<g, 128>>>(out);
}